// round 17
// baseline (speedup 1.0000x reference)
#include <cuda_runtime.h>
#include <cuda_fp16.h>
#include <cstdint>
#include <math.h>

#define BSZ 4096
#define TT  24
#define HID 1024
#define H3  3072
#define KBW 1088          // 1024 (h) + 1 dec + 12 aux + 1 bias + pad -> 17*64
#define CHUNKS 17         // KBW / 64
#define STAGES 2
#define GRU_WARPS 8

// ---------------- device globals (no cudaMalloc anywhere) ----------------
__device__ __half g_Ah[(size_t)BSZ * KBW];   // [h | dec | aux | 1 | pad] fp16
__device__ __half g_Wh[(size_t)H3 * KBW];    // combined weights fp16
__device__ __half g_gates[(size_t)BSZ * H3]; // GEMM out: [r | z | h_n] fp16
__device__ float g_H[(size_t)BSZ * HID];     // fp32 hidden state
__device__ __half g_inaux[(size_t)TT * BSZ * HID];  // aux-part of i_n, all steps
__device__ float g_loss;

__device__ __forceinline__ float tanh_fast(float x) {
    float y;
    asm("tanh.approx.f32 %0, %1;" : "=f"(y) : "f"(x));
    return y;
}
__device__ __forceinline__ float sigmoid_fast(float x) {
    return 0.5f * tanh_fast(0.5f * x) + 0.5f;
}

// ---------------- PTX helpers (compute_100-safe only) ----------------
__device__ __forceinline__ uint32_t smem_u32(const void* p) {
    uint32_t a;
    asm("{ .reg .u64 t; cvta.to.shared.u64 t, %1; cvt.u32.u64 %0, t; }" : "=r"(a) : "l"(p));
    return a;
}
__device__ __forceinline__ void cp_async16(uint32_t dst, const void* src) {
    asm volatile("cp.async.cg.shared.global [%0], [%1], 16;\n" :: "r"(dst), "l"(src));
}
__device__ __forceinline__ void cp_commit() { asm volatile("cp.async.commit_group;\n"); }
template <int N> __device__ __forceinline__ void cp_waitg() {
    asm volatile("cp.async.wait_group %0;\n" :: "n"(N));
}
__device__ __forceinline__ void ldm_x4(uint32_t& r0, uint32_t& r1, uint32_t& r2, uint32_t& r3,
                                       uint32_t addr) {
    asm volatile("ldmatrix.sync.aligned.m8n8.x4.shared.b16 {%0,%1,%2,%3}, [%4];"
                 : "=r"(r0), "=r"(r1), "=r"(r2), "=r"(r3) : "r"(addr));
}
__device__ __forceinline__ void mma_f16(float& c0, float& c1, float& c2, float& c3,
                                        uint32_t a0, uint32_t a1, uint32_t a2, uint32_t a3,
                                        uint32_t b0, uint32_t b1) {
    asm volatile("mma.sync.aligned.m16n8k16.row.col.f32.f16.f16.f32 "
                 "{%0,%1,%2,%3}, {%4,%5,%6,%7}, {%8,%9}, {%0,%1,%2,%3};"
                 : "+f"(c0), "+f"(c1), "+f"(c2), "+f"(c3)
                 : "r"(a0), "r"(a1), "r"(a2), "r"(a3), "r"(b0), "r"(b1));
}
__device__ __forceinline__ uint32_t sw128(uint32_t bo) { return bo ^ ((bo >> 3) & 0x70); }

// ---------------------------------------------------------------------------
// Init: A <- fp16(hn), g_H <- hn, pads <- 0, t=0 x-columns, loss <- 0
// ---------------------------------------------------------------------------
__global__ void k_init(const float* __restrict__ hn, const float* __restrict__ cur_pm,
                       const float* __restrict__ aux) {
    int row = blockIdx.x;
    int tid = threadIdx.x;
    __half* Ab = g_Ah + (size_t)row * KBW;
    for (int j = tid; j < HID; j += blockDim.x) {
        float x = hn[row * HID + j];
        Ab[j] = __float2half(x);
        g_H[row * HID + j] = x;
    }
    if (tid < 50) Ab[1038 + tid] = __float2half(0.0f);  // 1038..1087
    if (tid < 14) {
        float xv = (tid == 0) ? cur_pm[row]
                 : (tid == 13) ? 1.0f
                 : aux[(row * TT + 0) * 12 + (tid - 1)];
        Ab[1024 + tid] = __float2half(xv);
    }
    if (tid == 0 && row == 0) g_loss = 0.0f;
}

// ---------------------------------------------------------------------------
// Build W fp16 [3072 x 1088]
// ---------------------------------------------------------------------------
__global__ void k_wbf(const float* __restrict__ W_hh, const float* __restrict__ W_ih,
                      const float* __restrict__ b_ih, const float* __restrict__ b_hh) {
    size_t total = (size_t)H3 * KBW;
    for (size_t idx = (size_t)blockIdx.x * blockDim.x + threadIdx.x; idx < total;
         idx += (size_t)gridDim.x * blockDim.x) {
        int c = (int)(idx / KBW);
        int kk = (int)(idx - (size_t)c * KBW);
        float val;
        if (kk < 1024) val = W_hh[c * 1024 + kk];
        else if (kk <= 1036) val = (c < 2048) ? W_ih[c * 13 + (kk - 1024)] : 0.0f;
        else if (kk == 1037) val = (c < 2048) ? (b_ih[c] + b_hh[c]) : b_hh[c];
        else val = 0.0f;
        g_Wh[idx] = __float2half(val);
    }
}

// ---------------------------------------------------------------------------
// Precompute aux-part of i_n for ALL steps (fp16 out):
//   g_inaux[t][row][j] = b_ih[2048+j] + sum_f aux[row,t,f] * W_ih[(2048+j)*13 + 1 + f]
// ---------------------------------------------------------------------------
__global__ void __launch_bounds__(256) k_inaux(const float* __restrict__ aux,
                                               const float* __restrict__ W_ih,
                                               const float* __restrict__ b_ih) {
    extern __shared__ float wt[];  // wt[c*1024 + j]
    int tid = threadIdx.x;
    for (int idx = tid; idx < 13 * HID; idx += 256) {
        int c = idx >> 10, j = idx & 1023;
        wt[idx] = (c == 0) ? b_ih[2048 + j] : W_ih[(2048 + j) * 13 + c];
    }
    __syncthreads();
    int t = blockIdx.x;
    int lane = tid & 31, wid = tid >> 5;
    for (int rr = 0; rr < 8; rr++) {
        int row = blockIdx.y * 64 + wid * 8 + rr;
        float ax[12];
#pragma unroll
        for (int f = 0; f < 12; f++) ax[f] = aux[(row * TT + t) * 12 + f];
        __half* out = g_inaux + ((size_t)t * BSZ + row) * HID;
#pragma unroll 2
        for (int j = lane; j < HID; j += 32) {
            float s = wt[j];
#pragma unroll
            for (int f = 0; f < 12; f++) s = fmaf(ax[f], wt[(f + 1) * HID + j], s);
            out[j] = __float2half(s);
        }
    }
}

// ---------------------------------------------------------------------------
// Tensor-core GEMM via mma.sync (fp16 operands, fp32 accum, fp16 output):
//   gates[m][n] = sum_k A[m][k] * W[n][k],  K = 1088 (17 chunks)
// 128x128 CTA tile, block 128 (4 warps, 2x2 of 64x64 warp tiles).
// 2-stage cp.async pipeline (64KB smem) -> 3 CTAs/SM (3 warps/SMSP cross-hide
// barrier/waitg/LDSM stalls). Distance-1 prefetch: fill c+1 after the barrier,
// compute c overlaps its cp.asyncs. Single fragment buffer (fits 170-reg cap).
// ---------------------------------------------------------------------------
__global__ void __launch_bounds__(128, 3) k_gemm_mma() {
    extern __shared__ char smem[];
    uint32_t sb = smem_u32(smem);
    const int tid = threadIdx.x;      // 0..127
    const int wid = tid >> 5;         // 0..3
    const int lane = tid & 31;
    const int bn = blockIdx.x * 128;  // 24 N-tiles
    const int bm = blockIdx.y * 128;  // 32 M-tiles
    const int wm = wid >> 1;          // 0..1 -> 64-row slab
    const int wn = wid & 1;           // 0..1 -> 64-col slab

    const __half* Ag = g_Ah + (size_t)bm * KBW;
    const __half* Wg = g_Wh + (size_t)bn * KBW;

    float acc[4][8][4];
#pragma unroll
    for (int i = 0; i < 4; i++)
#pragma unroll
        for (int j = 0; j < 8; j++)
#pragma unroll
            for (int v2 = 0; v2 < 4; v2++) acc[i][j][v2] = 0.0f;

    const int rA = (lane & 7) + ((lane >> 3) & 1) * 8;
    const int cA = (lane >> 4) * 16;
    const int rB = lane & 7;
    const int hB = ((lane >> 3) & 1) * 16;
    const int pB = (lane >> 4);

#define FILL(s, c) do {                                                          \
    uint32_t _ab = sb + (uint32_t)(s) * 32768u;                                  \
    uint32_t _bb = _ab + 16384u;                                                 \
    _Pragma("unroll")                                                            \
    for (int q = 0; q < 8; q++) {                                                \
        int i = tid + q * 128;                                                   \
        int row = i >> 3, seg = i & 7;                                           \
        uint32_t bo = (uint32_t)(row * 128 + seg * 16);                          \
        uint32_t sw = sw128(bo);                                                 \
        const char* ga = (const char*)(Ag + (size_t)row * KBW + (c) * 64) + seg * 16; \
        const char* gb = (const char*)(Wg + (size_t)row * KBW + (c) * 64) + seg * 16; \
        cp_async16(_ab + sw, ga);                                                \
        cp_async16(_bb + sw, gb);                                                \
    }                                                                            \
} while (0)

    FILL(0, 0); cp_commit();

    for (int c = 0; c < CHUNKS; c++) {
        // In-flight at this point: chunk c only. Wait for it, then the barrier
        // (a) publishes chunk c to all warps and (b) certifies stage (c+1)&1
        // (last read during iter c-1) is reusable before refilling it.
        cp_waitg<0>();
        __syncthreads();
        if (c + 1 < CHUNKS) {
            FILL((c + 1) & 1, c + 1);
            cp_commit();
        }

        uint32_t ab = sb + (uint32_t)(c & 1) * 32768u;
        uint32_t bb = ab + 16384u;

        uint32_t af[4][4];
        uint32_t bfr[8][2];

#pragma unroll
        for (int kk = 0; kk < 4; kk++) {
#pragma unroll
            for (int mt = 0; mt < 4; mt++) {
                uint32_t bo = (uint32_t)((wm * 64 + mt * 16 + rA) * 128 + kk * 32 + cA);
                ldm_x4(af[mt][0], af[mt][1], af[mt][2], af[mt][3], ab + sw128(bo));
            }
#pragma unroll
            for (int ntp = 0; ntp < 4; ntp++) {
                uint32_t bo = (uint32_t)((wn * 64 + (ntp * 2 + pB) * 8 + rB) * 128 + kk * 32 + hB);
                ldm_x4(bfr[ntp * 2][0], bfr[ntp * 2][1],
                       bfr[ntp * 2 + 1][0], bfr[ntp * 2 + 1][1],
                       bb + sw128(bo));
            }
#pragma unroll
            for (int mt = 0; mt < 4; mt++)
#pragma unroll
                for (int nt = 0; nt < 8; nt++)
                    mma_f16(acc[mt][nt][0], acc[mt][nt][1], acc[mt][nt][2], acc[mt][nt][3],
                            af[mt][0], af[mt][1], af[mt][2], af[mt][3],
                            bfr[nt][0], bfr[nt][1]);
        }
    }
#undef FILL

    int quad = lane >> 2;
    int tig = lane & 3;
#pragma unroll
    for (int mt = 0; mt < 4; mt++) {
        int row0 = bm + wm * 64 + mt * 16 + quad;
#pragma unroll
        for (int nt = 0; nt < 8; nt++) {
            int col = bn + wn * 64 + nt * 8 + tig * 2;
            *(__half2*)&g_gates[(size_t)row0 * H3 + col] =
                __floats2half2_rn(acc[mt][nt][0], acc[mt][nt][1]);
            *(__half2*)&g_gates[(size_t)(row0 + 8) * H3 + col] =
                __floats2half2_rn(acc[mt][nt][2], acc[mt][nt][3]);
        }
    }
}

// ---------------------------------------------------------------------------
// Warp-per-row GRU elementwise + reductions + fused x-fill for step t+1.
// i_n = g_inaux[t][row] + dec * w1.  smem = w1 (4KB) + ew (24KB) -> 28KB.
// ---------------------------------------------------------------------------
__global__ void __launch_bounds__(256) k_gru_w(
    const float* __restrict__ W_ih, const float* __restrict__ emb,
    const float* __restrict__ W_out, const float* __restrict__ b_out,
    const int* __restrict__ st, const float* __restrict__ aux,
    const float* __restrict__ tgt_seq, const float* __restrict__ v,
    float* __restrict__ outp, int t)
{
    extern __shared__ float sh[];
    float* w1 = sh;            // [1024]: W_ih[(2048+j)*13 + 0]  (dec column)
    float* ew = sh + HID;      // j*6: [emb0..emb4 | W_out]
    __shared__ float sloss;
    int tid = threadIdx.x;

    for (int j = tid; j < HID; j += 256) w1[j] = W_ih[(2048 + j) * 13];
    for (int idx = tid; idx < HID * 6; idx += 256) {
        int j = idx / 6, c = idx - j * 6;
        ew[idx] = (c < 5) ? emb[c * HID + j] : W_out[j];
    }
    if (tid == 0) sloss = 0.0f;
    __syncthreads();

    int lane = tid & 31;
    int wid = tid >> 5;
    int row = blockIdx.x * GRU_WARPS + wid;

    const __half* gr = g_gates + (size_t)row * H3;
    const __half* inx = g_inaux + ((size_t)t * BSZ + row) * HID;
    __half* Ab = g_Ah + (size_t)row * KBW;
    float* Hrow = g_H + (size_t)row * HID;

    float dec = __half2float(Ab[1024]);

    float e0 = 0.f, e1 = 0.f, e2 = 0.f, e3 = 0.f, e4 = 0.f, od = 0.f;

#pragma unroll 4
    for (int j = lane; j < HID; j += 32) {
        float r = sigmoid_fast(__half2float(gr[j]));
        float z = sigmoid_fast(__half2float(gr[1024 + j]));
        float in_ = fmaf(dec, w1[j], __half2float(inx[j]));
        float n = tanh_fast(fmaf(r, __half2float(gr[2048 + j]), in_));
        float hp = Hrow[j];
        float h = (1.0f - z) * n + z * hp;
        Hrow[j] = h;
        Ab[j] = __float2half(h);
        const float* e = &ew[j * 6];
        e0 = fmaf(h, e[0], e0);
        e1 = fmaf(h, e[1], e1);
        e2 = fmaf(h, e[2], e2);
        e3 = fmaf(h, e[3], e3);
        e4 = fmaf(h, e[4], e4);
        od = fmaf(h, e[5], od);
    }

    float vals[6] = {e0, e1, e2, e3, e4, od};
#pragma unroll
    for (int s = 16; s > 0; s >>= 1)
#pragma unroll
        for (int vv = 0; vv < 6; vv++)
            vals[vv] += __shfl_down_sync(0xffffffffu, vals[vv], s);

    float o = 0.0f;
    if (lane == 0) {
        float mx = vals[0];
#pragma unroll
        for (int k2 = 1; k2 < 5; k2++) mx = fmaxf(mx, vals[k2]);
        float se = 0.f;
#pragma unroll
        for (int k2 = 0; k2 < 5; k2++) se += __expf(vals[k2] - mx);
        float lse = mx + __logf(se);
        int pos = st[row * TT + t];
        atomicAdd(&sloss, lse - vals[pos]);
        o = vals[5] + b_out[0];
        outp[row * TT + t] = o;
    }
    o = __shfl_sync(0xffffffffu, o, 0);

    // fused x-fill for step t+1
    if (t + 1 < TT && lane < 14) {
        float xv;
        if (lane == 0) {
            float tg = tgt_seq[row * TT + t];
            float m = (tg != 0.0f) ? v[row * TT + t + 1] : 0.0f;
            xv = (m == 1.0f) ? tg : o;
        } else if (lane == 13) {
            xv = 1.0f;
        } else {
            xv = aux[(row * TT + t + 1) * 12 + (lane - 1)];
        }
        Ab[1024 + lane] = __float2half(xv);
    }

    __syncthreads();
    if (tid == 0) atomicAdd(&g_loss, sloss);
}

// ---------------------------------------------------------------------------
__global__ void k_final(float* outp, int out_size) {
    if (out_size > BSZ * TT)
        outp[BSZ * TT] = g_loss * (1.0f / ((float)BSZ * (float)TT));
}

// ---------------------------------------------------------------------------
extern "C" void kernel_launch(void* const* d_in, const int* in_sizes, int n_in,
                              void* d_out, int out_size) {
    const float* aux    = (const float*)d_in[0];
    const float* cur_pm = (const float*)d_in[1];
    const float* hn     = (const float*)d_in[2];
    const int*   st     = (const int*)  d_in[3];
    const float* tgt    = (const float*)d_in[4];
    const float* v      = (const float*)d_in[5];
    const float* W_ih   = (const float*)d_in[6];
    const float* W_hh   = (const float*)d_in[7];
    const float* b_ih   = (const float*)d_in[8];
    const float* b_hh   = (const float*)d_in[9];
    const float* emb    = (const float*)d_in[10];
    const float* W_out  = (const float*)d_in[11];
    const float* b_out  = (const float*)d_in[12];
    float* outp = (float*)d_out;

    const int gemm_smem  = STAGES * 32768;       // 64 KB -> 3 CTAs/SM
    const int gru_smem   = (HID + HID * 6) * 4;  // 28 KB
    const int inaux_smem = 13 * HID * 4;         // 52 KB
    cudaFuncSetAttribute(k_gru_w, cudaFuncAttributeMaxDynamicSharedMemorySize, gru_smem);
    cudaFuncSetAttribute(k_gemm_mma, cudaFuncAttributeMaxDynamicSharedMemorySize, gemm_smem);
    cudaFuncSetAttribute(k_inaux, cudaFuncAttributeMaxDynamicSharedMemorySize, inaux_smem);

    k_init<<<BSZ, 256>>>(hn, cur_pm, aux);
    k_wbf<<<2048, 256>>>(W_hh, W_ih, b_ih, b_hh);
    {
        dim3 gi(TT, BSZ / 64);
        k_inaux<<<gi, 256, inaux_smem>>>(aux, W_ih, b_ih);
    }

    dim3 gg(H3 / 128, BSZ / 128);
    for (int t = 0; t < TT; t++) {
        k_gemm_mma<<<gg, 128, gemm_smem>>>();
        k_gru_w<<<BSZ / GRU_WARPS, 256, gru_smem>>>(W_ih, emb, W_out, b_out, st,
                                                    aux, tgt, v, outp, t);
    }
    k_final<<<1, 1>>>(outp, out_size);
}